// round 15
// baseline (speedup 1.0000x reference)
#include <cuda_runtime.h>
#include <cuda_fp16.h>
#include <cstdint>

#define B_    16
#define CIN   32
#define COUT  32
#define H_    256
#define W_    256
#define HW    (H_ * W_)
#define EMB2  512

__device__ float g_wadapt[B_ * CIN];
__device__ float g_bfinal[B_ * COUT];
// B fragments (single fp16): [b][g=tap*2+ks (18)][fp (2)][lane (32)] uint4
__device__ uint4 g_bfrag2[B_ * 18 * 2 * 32];

// ---------------------------------------------------------------------------
// PTX helpers (generic, sm_80+)
// ---------------------------------------------------------------------------
__device__ __forceinline__ uint32_t smem_u32(const void* p) {
    uint32_t a;
    asm("{ .reg .u64 t; cvta.to.shared.u64 t, %1; cvt.u32.u64 %0, t; }"
        : "=r"(a) : "l"(p));
    return a;
}
__device__ __forceinline__ void ldsm4(uint32_t* r, uint32_t a) {
    asm volatile("ldmatrix.sync.aligned.m8n8.x4.shared.b16 {%0,%1,%2,%3}, [%4];"
                 : "=r"(r[0]), "=r"(r[1]), "=r"(r[2]), "=r"(r[3]) : "r"(a));
}
__device__ __forceinline__ void ldsm2(uint32_t* r, uint32_t a) {
    asm volatile("ldmatrix.sync.aligned.m8n8.x2.shared.b16 {%0,%1}, [%2];"
                 : "=r"(r[0]), "=r"(r[1]) : "r"(a));
}
__device__ __forceinline__ void mma16816(float* d, const uint32_t* a,
                                         uint32_t b0, uint32_t b1) {
    asm volatile(
        "mma.sync.aligned.m16n8k16.row.col.f32.f16.f16.f32 "
        "{%0,%1,%2,%3}, {%4,%5,%6,%7}, {%8,%9}, {%0,%1,%2,%3};"
        : "+f"(d[0]), "+f"(d[1]), "+f"(d[2]), "+f"(d[3])
        : "r"(a[0]), "r"(a[1]), "r"(a[2]), "r"(a[3]), "r"(b0), "r"(b1));
}
__device__ __forceinline__ uint32_t pack_h2(__half a, __half b) {
    return (uint32_t)__half_as_ushort(a) |
           ((uint32_t)__half_as_ushort(b) << 16);
}

// ---------------------------------------------------------------------------
// Kernel A: adapt GEMVs, warp-per-dot (1024 dots, 128 CTAs x 256 thr).
// ---------------------------------------------------------------------------
__global__ void adapt_kernel(const float* __restrict__ cond,
                             const float* __restrict__ lpe,
                             const float* __restrict__ wa_w,
                             const float* __restrict__ wa_b,
                             const float* __restrict__ ba_w,
                             const float* __restrict__ ba_b,
                             const float* __restrict__ bias) {
    int gw   = blockIdx.x * (blockDim.x >> 5) + (threadIdx.x >> 5);
    int lane = threadIdx.x & 31;
    if (gw >= 2 * B_ * CIN) return;
    int isB = (gw >= B_ * CIN);
    int idx = isB ? gw - B_ * CIN : gw;
    int b = idx >> 5, c = idx & 31;

    const float4* w4 = (const float4*)((isB ? ba_w : wa_w) + c * EMB2);
    const float4* c4 = (const float4*)(cond + b * 256);
    const float4* l4 = (const float4*)(lpe  + b * 256);

    float s = 0.f;
#pragma unroll
    for (int k = 0; k < 4; k++) {
        int j = lane + 32 * k;
        float4 iv = (j < 64) ? c4[j] : l4[j - 64];
        float4 wv = w4[j];
        s += iv.x * wv.x + iv.y * wv.y + iv.z * wv.z + iv.w * wv.w;
    }
#pragma unroll
    for (int off = 16; off; off >>= 1) s += __shfl_xor_sync(0xffffffffu, s, off);

    if (lane == 0) {
        if (isB) g_bfinal[idx] = bias[c] * (s + ba_b[c]);
        else     g_wadapt[idx] = s + wa_b[c];
    }
}

// ---------------------------------------------------------------------------
// Kernel A2: fragment emission. Grid (9 taps, 16 batches), 128 thr.
// Reads precomputed g_wadapt; builds scaled fp16 B slice; emits fragments.
// ---------------------------------------------------------------------------
__global__ void __launch_bounds__(128)
emit_kernel(const float* __restrict__ weights) {
    __shared__ char smB[32 * 128];
    const int tid  = threadIdx.x;
    const int warp = tid >> 5;
    const int lane = tid & 31;
    const int kl   = blockIdx.x;
    const int b    = blockIdx.y;

    for (int e = tid; e < 32 * 32; e += 128) {
        int ci = e >> 5;
        int o  = e & 31;
        float v = weights[(ci * 32 + o) * 9 + kl] * g_wadapt[b * CIN + ci];
        int ch = (ci >> 3) ^ (o & 7);
        int wb = (ci & 7) * 2;
        *(__half*)(smB + o * 128 + ch * 16 + wb) = __float2half(v);
    }
    __syncthreads();

    const uint32_t sbB = smem_u32(smB);
    uint2* dst = (uint2*)g_bfrag2;
    for (int s = warp; s < 8; s += 4) {
        int ks = s >> 2, nt = s & 3;
        int r  = nt * 8 + (lane & 7);
        int c0 = ks * 2 + ((lane >> 3) & 1);
        uint32_t f[2];
        ldsm2(f, sbB + r * 128 + (uint32_t)((c0 ^ (r & 7)) << 4));
        int g = kl * 2 + ks;
        dst[((((size_t)b * 18 + g) * 2 + (nt >> 1)) * 32 + lane) * 2 + (nt & 1)] =
            make_uint2(f[0], f[1]);
    }
}

// ---------------------------------------------------------------------------
// Conv mainloop. CTA = batch b, 8 rows x 64 cols, all 32 Cout; 256 thr =
// 8 warps; warp w owns row w (4 m-tiles); 3 CTAs/SM.
// A smem: 660 pixel-rows x 64B (32 fp16), 16B chunks XOR-swizzled by
// ((p>>1)&3)  — conflict-free for ldsm (bank group = p mod 8, injective).
// D = A*B single fp16 product: 4 MMAs per (tap,ks,mt).
// ---------------------------------------------------------------------------
#define APIX   660                 // 10 * 66
#define ABYTES (APIX * 64)         // 42240
#define SMEM_TOTAL 65536           // >= max(ABYTES, 8 warps * 8KB scratch)
#define NTHR 256

__global__ void __launch_bounds__(NTHR, 3)
conv_mma(const float* __restrict__ x,
         float* __restrict__ out) {
    extern __shared__ __align__(128) char smA[];
    __shared__ float bfc[COUT];

    const int tid  = threadIdx.x;
    const int warp = tid >> 5;
    const int lane = tid & 31;
    const int b    = blockIdx.z;
    const int gy0  = blockIdx.y * 8;
    const int gx0  = blockIdx.x * 64;

    if (tid < COUT) bfc[tid] = g_bfinal[b * COUT + tid];

    // ---- Stage A: per pixel-row, 4 ci-octets -> 1x STS.128 each ----
    const float* xb = x + (size_t)b * CIN * HW;
    for (int p = tid; p < APIX; p += NTHR) {
        const int iy = p / 66;
        const int ix = p - iy * 66;
        const int gy = gy0 - 1 + iy;
        const int gx = gx0 - 1 + ix;
        const bool ok = (unsigned)gy < (unsigned)H_ && (unsigned)gx < (unsigned)W_;
        const float* px = xb + (size_t)(ok ? gy * W_ + gx : 0);
        char* arow = smA + p * 64;
        const int psw = (p >> 1) & 3;
#pragma unroll
        for (int c = 0; c < 4; c++) {
            float v[8];
#pragma unroll
            for (int j = 0; j < 8; j++)
                v[j] = ok ? px[(size_t)(8 * c + j) * HW] : 0.f;
            __half h[8];
#pragma unroll
            for (int j = 0; j < 8; j++) h[j] = __float2half(v[j]);
            uint4 hv;
            hv.x = pack_h2(h[0], h[1]);
            hv.y = pack_h2(h[2], h[3]);
            hv.z = pack_h2(h[4], h[5]);
            hv.w = pack_h2(h[6], h[7]);
            *(uint4*)(arow + ((c ^ psw) << 4)) = hv;
        }
    }
    __syncthreads();

    // ---- MMA mainloop: 4 m-tiles share every B-fragment load ----
    const uint32_t sbA = smem_u32(smA);
    const int kh = lane >> 4;
    const uint4* __restrict__ bfb = g_bfrag2 + (size_t)b * 18 * 2 * 32 + lane;
    const int pbase = warp * 66 + (lane & 15);

    float acc[4][4][4];
#pragma unroll
    for (int mt = 0; mt < 4; mt++)
#pragma unroll
        for (int nt = 0; nt < 4; nt++)
#pragma unroll
            for (int j = 0; j < 4; j++) acc[mt][nt][j] = 0.f;

#pragma unroll
    for (int tap = 0; tap < 9; tap++) {
        const int pshift = (tap / 3) * 66 + (tap % 3);
#pragma unroll
        for (int ks = 0; ks < 2; ks++) {
            const uint4* bp = bfb + (size_t)(tap * 2 + ks) * 2 * 32;
            uint4 q0 = bp[0 * 32];     // nt0 (.xy), nt1 (.zw)
            uint4 q1 = bp[1 * 32];     // nt2 (.xy), nt3 (.zw)

#pragma unroll
            for (int mt = 0; mt < 4; mt++) {
                const int pa = pbase + mt * 16 + pshift;
                const uint32_t arow = sbA + pa * 64;
                const int     psw  = (pa >> 1) & 3;
                uint32_t ah[4];
                ldsm4(ah, arow + (uint32_t)((((ks * 2 + kh) ^ psw)) << 4));

                mma16816(acc[mt][0], ah, q0.x, q0.y);
                mma16816(acc[mt][1], ah, q0.z, q0.w);
                mma16816(acc[mt][2], ah, q1.x, q1.y);
                mma16816(acc[mt][3], ah, q1.z, q1.w);
            }
        }
    }

    // ---- Epilogue: warp-private smem transpose -> coalesced STG.128 ----
    __syncthreads();   // all warps done reading A tile
    float* scratch = (float*)smA + warp * 2048;   // 8KB per warp

#pragma unroll
    for (int mt = 0; mt < 4; mt++) {
#pragma unroll
        for (int nt = 0; nt < 4; nt++) {
#pragma unroll
            for (int j = 0; j < 4; j++) {
                int o   = nt * 8 + (lane & 3) * 2 + (j & 1);
                int pix = mt * 16 + (j >> 1) * 8 + (lane >> 2);
                scratch[o * 64 + pix] = acc[mt][nt][j] + bfc[o];
            }
        }
    }
    __syncwarp();

    const int gy = gy0 + warp;
    float* ob = out + (size_t)b * COUT * HW + (size_t)gy * W_ + gx0;
#pragma unroll
    for (int k = 0; k < 16; k++) {
        int o  = 2 * k + (lane >> 4);
        int xl = (lane & 15) * 4;
        float4 v = *(float4*)&scratch[o * 64 + xl];
        *(float4*)(ob + (size_t)o * HW + xl) = v;
    }
}

// ---------------------------------------------------------------------------
extern "C" void kernel_launch(void* const* d_in, const int* in_sizes, int n_in,
                              void* d_out, int out_size) {
    const float* x    = (const float*)d_in[0];
    const float* cond = (const float*)d_in[1];
    const float* lpe  = (const float*)d_in[2];
    const float* w    = (const float*)d_in[3];
    const float* bias = (const float*)d_in[4];
    const float* wa_w = (const float*)d_in[5];
    const float* wa_b = (const float*)d_in[6];
    const float* ba_w = (const float*)d_in[7];
    const float* ba_b = (const float*)d_in[8];
    float* out = (float*)d_out;

    cudaFuncSetAttribute(conv_mma,
                         cudaFuncAttributeMaxDynamicSharedMemorySize, SMEM_TOTAL);

    adapt_kernel<<<128, 256>>>(cond, lpe, wa_w, wa_b, ba_w, ba_b, bias);
    emit_kernel<<<dim3(9, B_), 128>>>(w);

    dim3 grid(W_ / 64, H_ / 8, B_);
    conv_mma<<<grid, NTHR, SMEM_TOTAL>>>(x, out);
}

// round 16
// speedup vs baseline: 1.3259x; 1.3259x over previous
#include <cuda_runtime.h>
#include <cuda_fp16.h>
#include <cstdint>

#define B_    16
#define CIN   32
#define COUT  32
#define H_    256
#define W_    256
#define HW    (H_ * W_)
#define EMB2  512

__device__ float g_wadapt[B_ * CIN];
__device__ float g_bfinal[B_ * COUT];
// B fragments (single fp16): [b][g=tap*2+ks (18)][fp (2)][lane (32)] uint4
__device__ uint4 g_bfrag2[B_ * 18 * 2 * 32];

// ---------------------------------------------------------------------------
// PTX helpers (generic, sm_80+)
// ---------------------------------------------------------------------------
__device__ __forceinline__ uint32_t smem_u32(const void* p) {
    uint32_t a;
    asm("{ .reg .u64 t; cvta.to.shared.u64 t, %1; cvt.u32.u64 %0, t; }"
        : "=r"(a) : "l"(p));
    return a;
}
__device__ __forceinline__ void ldsm4(uint32_t* r, uint32_t a) {
    asm volatile("ldmatrix.sync.aligned.m8n8.x4.shared.b16 {%0,%1,%2,%3}, [%4];"
                 : "=r"(r[0]), "=r"(r[1]), "=r"(r[2]), "=r"(r[3]) : "r"(a));
}
__device__ __forceinline__ void ldsm2(uint32_t* r, uint32_t a) {
    asm volatile("ldmatrix.sync.aligned.m8n8.x2.shared.b16 {%0,%1}, [%2];"
                 : "=r"(r[0]), "=r"(r[1]) : "r"(a));
}
__device__ __forceinline__ void mma16816(float* d, const uint32_t* a,
                                         uint32_t b0, uint32_t b1) {
    asm volatile(
        "mma.sync.aligned.m16n8k16.row.col.f32.f16.f16.f32 "
        "{%0,%1,%2,%3}, {%4,%5,%6,%7}, {%8,%9}, {%0,%1,%2,%3};"
        : "+f"(d[0]), "+f"(d[1]), "+f"(d[2]), "+f"(d[3])
        : "r"(a[0]), "r"(a[1]), "r"(a[2]), "r"(a[3]), "r"(b0), "r"(b1));
}
__device__ __forceinline__ uint32_t pack_h2(__half a, __half b) {
    return (uint32_t)__half_as_ushort(a) |
           ((uint32_t)__half_as_ushort(b) << 16);
}

// ---------------------------------------------------------------------------
// Kernel A: adapt GEMVs, warp-per-dot (1024 dots, 128 CTAs x 256 thr).
// ---------------------------------------------------------------------------
__global__ void adapt_kernel(const float* __restrict__ cond,
                             const float* __restrict__ lpe,
                             const float* __restrict__ wa_w,
                             const float* __restrict__ wa_b,
                             const float* __restrict__ ba_w,
                             const float* __restrict__ ba_b,
                             const float* __restrict__ bias) {
    int gw   = blockIdx.x * (blockDim.x >> 5) + (threadIdx.x >> 5);
    int lane = threadIdx.x & 31;
    if (gw >= 2 * B_ * CIN) return;
    int isB = (gw >= B_ * CIN);
    int idx = isB ? gw - B_ * CIN : gw;
    int b = idx >> 5, c = idx & 31;

    const float4* w4 = (const float4*)((isB ? ba_w : wa_w) + c * EMB2);
    const float4* c4 = (const float4*)(cond + b * 256);
    const float4* l4 = (const float4*)(lpe  + b * 256);

    float s = 0.f;
#pragma unroll
    for (int k = 0; k < 4; k++) {
        int j = lane + 32 * k;
        float4 iv = (j < 64) ? c4[j] : l4[j - 64];
        float4 wv = w4[j];
        s += iv.x * wv.x + iv.y * wv.y + iv.z * wv.z + iv.w * wv.w;
    }
#pragma unroll
    for (int off = 16; off; off >>= 1) s += __shfl_xor_sync(0xffffffffu, s, off);

    if (lane == 0) {
        if (isB) g_bfinal[idx] = bias[c] * (s + ba_b[c]);
        else     g_wadapt[idx] = s + wa_b[c];
    }
}

// ---------------------------------------------------------------------------
// Kernel A2: fragment emission. Grid (9 taps, 16 batches), 128 thr.
// Reads precomputed g_wadapt; builds scaled fp16 B slice; emits fragments.
// ---------------------------------------------------------------------------
__global__ void __launch_bounds__(128)
emit_kernel(const float* __restrict__ weights) {
    __shared__ char smB[32 * 128];
    const int tid  = threadIdx.x;
    const int warp = tid >> 5;
    const int lane = tid & 31;
    const int kl   = blockIdx.x;
    const int b    = blockIdx.y;

    for (int e = tid; e < 32 * 32; e += 128) {
        int ci = e >> 5;
        int o  = e & 31;
        float v = weights[(ci * 32 + o) * 9 + kl] * g_wadapt[b * CIN + ci];
        int ch = (ci >> 3) ^ (o & 7);
        int wb = (ci & 7) * 2;
        *(__half*)(smB + o * 128 + ch * 16 + wb) = __float2half(v);
    }
    __syncthreads();

    const uint32_t sbB = smem_u32(smB);
    uint2* dst = (uint2*)g_bfrag2;
    for (int s = warp; s < 8; s += 4) {
        int ks = s >> 2, nt = s & 3;
        int r  = nt * 8 + (lane & 7);
        int c0 = ks * 2 + ((lane >> 3) & 1);
        uint32_t f[2];
        ldsm2(f, sbB + r * 128 + (uint32_t)((c0 ^ (r & 7)) << 4));
        int g = kl * 2 + ks;
        dst[((((size_t)b * 18 + g) * 2 + (nt >> 1)) * 32 + lane) * 2 + (nt & 1)] =
            make_uint2(f[0], f[1]);
    }
}

// ---------------------------------------------------------------------------
// Conv mainloop (R14 proven config). CTA = batch b, 8 rows x 64 cols, all
// 32 Cout; 256 thr = 8 warps; warp w owns row w (4 m-tiles); 2 CTAs/SM.
// A smem: 660 pixel-rows x 128B, chunks 0-3 = 32 fp16, chunks 4-7 unused;
// 16B chunks XOR-swizzled by (p&7).
// D = A*B single fp16 product: 4 MMAs per (tap,ks,mt).
// ---------------------------------------------------------------------------
#define APIX   660                 // 10 * 66
#define ABYTES (APIX * 128)        // 84480
#define NTHR 256

__global__ void __launch_bounds__(NTHR, 2)
conv_mma(const float* __restrict__ x,
         float* __restrict__ out) {
    extern __shared__ __align__(128) char smA[];
    __shared__ float bfc[COUT];

    const int tid  = threadIdx.x;
    const int warp = tid >> 5;
    const int lane = tid & 31;
    const int b    = blockIdx.z;
    const int gy0  = blockIdx.y * 8;
    const int gx0  = blockIdx.x * 64;

    if (tid < COUT) bfc[tid] = g_bfinal[b * COUT + tid];

    // ---- Stage A: per pixel-row, 4 ci-octets -> 1x STS.128 each ----
    const float* xb = x + (size_t)b * CIN * HW;
    for (int p = tid; p < APIX; p += NTHR) {
        const int iy = p / 66;
        const int ix = p - iy * 66;
        const int gy = gy0 - 1 + iy;
        const int gx = gx0 - 1 + ix;
        const bool ok = (unsigned)gy < (unsigned)H_ && (unsigned)gx < (unsigned)W_;
        const float* px = xb + (size_t)(ok ? gy * W_ + gx : 0);
        char* arow = smA + p * 128;
        const int psw = p & 7;
#pragma unroll
        for (int c = 0; c < 4; c++) {
            float v[8];
#pragma unroll
            for (int j = 0; j < 8; j++)
                v[j] = ok ? px[(size_t)(8 * c + j) * HW] : 0.f;
            __half h[8];
#pragma unroll
            for (int j = 0; j < 8; j++) h[j] = __float2half(v[j]);
            uint4 hv;
            hv.x = pack_h2(h[0], h[1]);
            hv.y = pack_h2(h[2], h[3]);
            hv.z = pack_h2(h[4], h[5]);
            hv.w = pack_h2(h[6], h[7]);
            *(uint4*)(arow + ((c ^ psw) << 4)) = hv;
        }
    }
    __syncthreads();

    // ---- MMA mainloop: 4 m-tiles share every B-fragment load ----
    const uint32_t sbA = smem_u32(smA);
    const int kh = lane >> 4;
    const uint4* __restrict__ bfb = g_bfrag2 + (size_t)b * 18 * 2 * 32 + lane;
    const int pbase = warp * 66 + (lane & 15);

    float acc[4][4][4];
#pragma unroll
    for (int mt = 0; mt < 4; mt++)
#pragma unroll
        for (int nt = 0; nt < 4; nt++)
#pragma unroll
            for (int j = 0; j < 4; j++) acc[mt][nt][j] = 0.f;

#pragma unroll
    for (int tap = 0; tap < 9; tap++) {
        const int pshift = (tap / 3) * 66 + (tap % 3);
#pragma unroll
        for (int ks = 0; ks < 2; ks++) {
            const uint4* bp = bfb + (size_t)(tap * 2 + ks) * 2 * 32;
            uint4 q0 = bp[0 * 32];     // nt0 (.xy), nt1 (.zw)
            uint4 q1 = bp[1 * 32];     // nt2 (.xy), nt3 (.zw)

#pragma unroll
            for (int mt = 0; mt < 4; mt++) {
                const int pa = pbase + mt * 16 + pshift;
                const uint32_t arow = sbA + pa * 128;
                const int     psw  = pa & 7;
                uint32_t ah[4];
                ldsm4(ah, arow + (uint32_t)(((ks * 2 + kh) ^ psw) << 4));

                mma16816(acc[mt][0], ah, q0.x, q0.y);
                mma16816(acc[mt][1], ah, q0.z, q0.w);
                mma16816(acc[mt][2], ah, q1.x, q1.y);
                mma16816(acc[mt][3], ah, q1.z, q1.w);
            }
        }
    }

    // ---- Epilogue: warp-private smem transpose -> coalesced STG.128 ----
    __syncthreads();   // all warps done reading A tile
    float* scratch = (float*)smA + warp * 2048;   // 8KB per warp

#pragma unroll
    for (int mt = 0; mt < 4; mt++) {
#pragma unroll
        for (int nt = 0; nt < 4; nt++) {
#pragma unroll
            for (int j = 0; j < 4; j++) {
                int o   = nt * 8 + (lane & 3) * 2 + (j & 1);
                int pix = mt * 16 + (j >> 1) * 8 + (lane >> 2);
                scratch[o * 64 + pix] = acc[mt][nt][j] + bfc[o];
            }
        }
    }
    __syncwarp();

    const int gy = gy0 + warp;
    float* ob = out + (size_t)b * COUT * HW + (size_t)gy * W_ + gx0;
#pragma unroll
    for (int k = 0; k < 16; k++) {
        int o  = 2 * k + (lane >> 4);
        int xl = (lane & 15) * 4;
        float4 v = *(float4*)&scratch[o * 64 + xl];
        *(float4*)(ob + (size_t)o * HW + xl) = v;
    }
}

// ---------------------------------------------------------------------------
extern "C" void kernel_launch(void* const* d_in, const int* in_sizes, int n_in,
                              void* d_out, int out_size) {
    const float* x    = (const float*)d_in[0];
    const float* cond = (const float*)d_in[1];
    const float* lpe  = (const float*)d_in[2];
    const float* w    = (const float*)d_in[3];
    const float* bias = (const float*)d_in[4];
    const float* wa_w = (const float*)d_in[5];
    const float* wa_b = (const float*)d_in[6];
    const float* ba_w = (const float*)d_in[7];
    const float* ba_b = (const float*)d_in[8];
    float* out = (float*)d_out;

    cudaFuncSetAttribute(conv_mma,
                         cudaFuncAttributeMaxDynamicSharedMemorySize, ABYTES);

    adapt_kernel<<<128, 256>>>(cond, lpe, wa_w, wa_b, ba_w, ba_b, bias);
    emit_kernel<<<dim3(9, B_), 128>>>(w);

    dim3 grid(W_ / 64, H_ / 8, B_);
    conv_mma<<<grid, NTHR, ABYTES>>>(x, out);
}